// round 15
// baseline (speedup 1.0000x reference)
#include <cuda_runtime.h>
#include <cuda_bf16.h>
#include <math.h>
#include <stdint.h>

#define BB 8192
#define NSEQ 29
#define FF 147
#define DD 128
#define DCAT 429
#define KPAD 432
#define NROWS (BB*NSEQ)
#define EPS_BN 1e-5f
#define APAD 434

// ---------------- scratch ----------------
__device__ float g_z[(size_t)NROWS * DD];   // raw z = xp@Wg, then overwritten in-place by u
__device__ float g_pool[BB * DD];
__device__ float g_p[BB * DD];
__device__ __nv_bfloat16 g_Bh[DD * KPAD];   // WgT hi split, [n][k] K-major, k padded to 432
__device__ __nv_bfloat16 g_Bl[DD * KPAD];   // WgT lo split
__device__ float g_s1[NSEQ], g_q1[NSEQ];
__device__ float g_is1[NSEQ], g_m1[NSEQ];
__device__ float g_S[DD];                   // colsum of Wg
__device__ float g_s2[NSEQ], g_q2[NSEQ];
__device__ float g_bn2m[NSEQ], g_bn2i[NSEQ];
__device__ float g_v[DD];
__device__ float g_s3[DD], g_q3[DD];
__device__ float g_bn3m[DD], g_bn3i[DD];

#define FMA2(d, a, b) asm("fma.rn.f32x2 %0, %1, %2, %0;" : "+l"(d) : "l"(a), "l"(b))
#define PACK2(d, f)   asm("mov.b64 %0, {%1, %1};" : "=l"(d) : "r"(__float_as_uint(f)))
#define UNPK(lo, hi, p) { unsigned _l,_h; asm("mov.b64 {%0,%1}, %2;":"=r"(_l),"=r"(_h):"l"(p)); lo=__uint_as_float(_l); hi=__uint_as_float(_h); }

#define MMA_BF16(c, a0, a1, a2, a3, b0, b1) \
    asm volatile("mma.sync.aligned.m16n8k16.row.col.f32.bf16.bf16.f32 " \
        "{%0,%1,%2,%3}, {%4,%5,%6,%7}, {%8,%9}, {%0,%1,%2,%3};" \
        : "+f"(c[0]), "+f"(c[1]), "+f"(c[2]), "+f"(c[3]) \
        : "r"(a0), "r"(a1), "r"(a2), "r"(a3), "r"(b0), "r"(b1))

__device__ __forceinline__ void cp_async16(unsigned saddr, const void* g) {
    asm volatile("cp.async.cg.shared.global [%0], [%1], 16;" :: "r"(saddr), "l"(g) : "memory");
}

__device__ __forceinline__ float conv_val(const float* __restrict__ xr, const float* __restrict__ w, int k) {
    float v;
    if (k < 145) {
        v = fmaf(xr[k], w[0], fmaf(xr[k+1], w[1], fmaf(xr[k+2], w[2], w[15])));
    } else if (k < 288) {
        int j = k - 145; v = w[16];
        #pragma unroll
        for (int u = 0; u < 5; u++) v = fmaf(xr[j+u], w[3+u], v);
    } else {
        int j = k - 288; v = w[17];
        #pragma unroll
        for (int u = 0; u < 7; u++) v = fmaf(xr[j+u], w[8+u], v);
    }
    return v;
}

__device__ __forceinline__ void load_ws(float* ws, const float* w1, const float* b1,
    const float* w2, const float* b2, const float* w3, const float* b3, const float* ac) {
    ws[0]=w1[0]; ws[1]=w1[1]; ws[2]=w1[2];
    ws[3]=w2[0]; ws[4]=w2[1]; ws[5]=w2[2]; ws[6]=w2[3]; ws[7]=w2[4];
    ws[8]=w3[0]; ws[9]=w3[1]; ws[10]=w3[2]; ws[11]=w3[3]; ws[12]=w3[4]; ws[13]=w3[5]; ws[14]=w3[6];
    ws[15]=b1[0]; ws[16]=b2[0]; ws[17]=b3[0]; ws[18]=ac[0];
}

// ---------------- k_reset ----------------
__global__ void k_reset() {
    int t = threadIdx.x;
    if (t < NSEQ) { g_s1[t]=0.f; g_q1[t]=0.f; g_s2[t]=0.f; g_q2[t]=0.f; }
    if (t < DD)   { g_s3[t]=0.f; g_q3[t]=0.f; }
}

// ---------------- k_prep: Wg -> transposed split-bf16, K padded ----------------
__global__ __launch_bounds__(256)
void k_prep(const float* __restrict__ Wg) {
    int i = blockIdx.x * 256 + threadIdx.x;     // 128*432
    if (i >= DD * KPAD) return;
    int n = i / KPAD, k = i % KPAD;
    float v = (k < DCAT) ? Wg[k * DD + n] : 0.f;
    __nv_bfloat16 h = __float2bfloat16(v);
    g_Bh[i] = h;
    g_Bl[i] = __float2bfloat16(v - __bfloat162float(h));
}

// ---------------- k_gemm: conv+prelu -> split-bf16 mma.sync GEMM -> raw z; BN1 stats -------
// smem bytes: Xs 64*149*4=38144 | Ah 64*434*2=55552 | Al 55552 | B 2*8192=16384  => 165632
#define XS_FLOATS (64*149)
#define AH_BYTES (64*APAD*2)
#define GEMM_SMEM (XS_FLOATS*4 + 2*AH_BYTES + 16384)

__global__ __launch_bounds__(256, 1)
void k_gemm(const float* __restrict__ X,
            const float* w1, const float* b1, const float* w2, const float* b2,
            const float* w3, const float* b3, const float* ac)
{
    extern __shared__ float sm[];
    float* Xs = sm;
    __nv_bfloat16* Ah = (__nv_bfloat16*)(sm + XS_FLOATS);
    __nv_bfloat16* Al = (__nv_bfloat16*)((char*)Ah + AH_BYTES);
    char* Bb = (char*)Al + AH_BYTES;            // 2 bufs x { Bh 4096 | Bl 4096 }
    __shared__ float ws[20];
    __shared__ float sS[64], sQ[64];

    int t = threadIdx.x;
    long row0 = (long)blockIdx.x * 64;
    unsigned sbB = (unsigned)__cvta_generic_to_shared(Bb);

    // prefetch B chunk 0
    for (int i = t; i < 512; i += 256) {
        int arr = i >> 8, rem = i & 255, n = rem >> 1, hf = rem & 1;
        const __nv_bfloat16* src = (arr ? g_Bl : g_Bh) + n*KPAD + hf*8;
        cp_async16(sbB + arr*4096 + n*32 + hf*16, src);
    }
    asm volatile("cp.async.commit_group;" ::: "memory");

    const float* Xb = X + row0 * FF;
    for (int e = t; e < 64*FF; e += 256) { int rr = e/FF, j = e - rr*FF; Xs[rr*149+j] = Xb[e]; }
    if (t == 0) load_ws(ws, w1,b1,w2,b2,w3,b3,ac);
    if (t < 64) { sS[t] = 0.f; sQ[t] = 0.f; }
    __syncthreads();

    // conv + prelu -> split bf16 A; fused BN1 stats (thread owns row t&63)
    {
        float a = ws[18];
        int rr = t & 63;
        const float* xr = Xs + rr*149;
        float ls = 0.f, lq = 0.f;
        for (int e = t; e < DCAT*64; e += 256) {
            int k = e >> 6;
            float v = conv_val(xr, ws, k);
            v = (v >= 0.f) ? v : a*v;
            __nv_bfloat16 h = __float2bfloat16(v);
            Ah[rr*APAD + k] = h;
            Al[rr*APAD + k] = __float2bfloat16(v - __bfloat162float(h));
            ls += v; lq = fmaf(v, v, lq);
        }
        atomicAdd(&sS[rr], ls);
        atomicAdd(&sQ[rr], lq);
        // zero-pad k = 429..431
        if (t < 192) {
            int pr = t / 3, pk = DCAT + t % 3;
            Ah[pr*APAD + pk] = __float2bfloat16(0.f);
            Al[pr*APAD + pk] = __float2bfloat16(0.f);
        }
    }
    __syncthreads();

    int wid = t >> 5, lane = t & 31;
    int wr = wid & 3, wc = wid >> 2;
    int gid = lane >> 2, tig = lane & 3;
    const __nv_bfloat16* ArH = Ah + (16*wr + gid)*APAD + 2*tig;
    const __nv_bfloat16* ArL = Al + (16*wr + gid)*APAD + 2*tig;

    float acc[8][4];
    #pragma unroll
    for (int j = 0; j < 8; j++)
        #pragma unroll
        for (int q = 0; q < 4; q++) acc[j][q] = 0.f;

    for (int c = 0; c < 27; ++c) {
        asm volatile("cp.async.wait_group 0;" ::: "memory");
        __syncthreads();
        if (c < 26) {
            int k1 = (c + 1) * 16;
            unsigned dstb = sbB + ((c + 1) & 1) * 8192;
            for (int i = t; i < 512; i += 256) {
                int arr = i >> 8, rem = i & 255, n = rem >> 1, hf = rem & 1;
                const __nv_bfloat16* src = (arr ? g_Bl : g_Bh) + n*KPAD + k1 + hf*8;
                cp_async16(dstb + arr*4096 + n*32 + hf*16, src);
            }
            asm volatile("cp.async.commit_group;" ::: "memory");
        }
        int k0 = c * 16;
        unsigned ah0 = *(const unsigned*)(ArH + k0);
        unsigned ah1 = *(const unsigned*)(ArH + 8*APAD + k0);
        unsigned ah2 = *(const unsigned*)(ArH + k0 + 8);
        unsigned ah3 = *(const unsigned*)(ArH + 8*APAD + k0 + 8);
        unsigned al0 = *(const unsigned*)(ArL + k0);
        unsigned al1 = *(const unsigned*)(ArL + 8*APAD + k0);
        unsigned al2 = *(const unsigned*)(ArL + k0 + 8);
        unsigned al3 = *(const unsigned*)(ArL + 8*APAD + k0 + 8);
        const __nv_bfloat16* BhS = (const __nv_bfloat16*)(Bb + (c & 1)*8192);
        const __nv_bfloat16* BlS = BhS + 2048;
        #pragma unroll
        for (int j = 0; j < 8; j++) {
            int n = wc*64 + j*8 + gid;
            const __nv_bfloat16* bph = BhS + n*16 + 2*tig;
            const __nv_bfloat16* bpl = BlS + n*16 + 2*tig;
            unsigned bh0 = *(const unsigned*)bph;
            unsigned bh1 = *(const unsigned*)(bph + 8);
            unsigned bl0 = *(const unsigned*)bpl;
            unsigned bl1 = *(const unsigned*)(bpl + 8);
            MMA_BF16(acc[j], ah0, ah1, ah2, ah3, bh0, bh1);
            MMA_BF16(acc[j], ah0, ah1, ah2, ah3, bl0, bl1);
            MMA_BF16(acc[j], al0, al1, al2, al3, bh0, bh1);
        }
    }

    // epilogue
    size_t rbase = (size_t)(row0 + 16*wr + gid) * DD + wc*64 + 2*tig;
    #pragma unroll
    for (int j = 0; j < 8; j++) {
        *(float2*)(g_z + rbase + j*8)          = make_float2(acc[j][0], acc[j][1]);
        *(float2*)(g_z + rbase + 8*DD + j*8)   = make_float2(acc[j][2], acc[j][3]);
    }

    if (t < 64) {
        int n = (int)((row0 + t) % NSEQ);
        atomicAdd(&g_s1[n], sS[t]);
        atomicAdd(&g_q1[n], sQ[t]);
    }
}

// ---------------- k_fin1: BN1 finalize + colsum S (1 block, 256 threads) ----------------
__global__ void k_fin1(const float* __restrict__ Wg) {
    __shared__ float Ssh[DD];
    int t = threadIdx.x;
    if (t < NSEQ) {
        float cnt = (float)BB * (float)DCAT;
        float m = g_s1[t] / cnt;
        float v = g_q1[t] / cnt - m*m;
        g_is1[t] = rsqrtf(v + EPS_BN);
        g_m1[t]  = m;
    }
    int d = t & 127, h = t >> 7;
    float S = 0.f;
    #pragma unroll 8
    for (int k = h; k < DCAT; k += 2) S += Wg[k*DD + d];
    if (h == 1) Ssh[d] = S;
    __syncthreads();
    if (h == 0) g_S[d] = S + Ssh[d];
}

// ---------------- k_mix: u = prelu(corr @ z_bn + bg) via rank-1 BN fold; BN2 stats ----------
__global__ __launch_bounds__(128)
void k_mix(const float* __restrict__ corr, const float* __restrict__ bg,
           const float* __restrict__ ag)
{
    __shared__ float2 cs[2*NSEQ*32];
    __shared__ float qs[2*32];
    __shared__ float ssum[2*32], ssq[2*32];
    __shared__ float i1s[32], m1s[32];

    int t = threadIdx.x;
    int lb = t >> 6, lt = t & 63;
    int b = blockIdx.x * 2 + lb;

    unsigned long long zz[32];
    const float* zb = g_z + (size_t)b * NSEQ * DD + 2*lt;
    #pragma unroll
    for (int m = 0; m < NSEQ; m++) zz[m] = *(const unsigned long long*)(zb + m*DD);
    zz[29] = 0ull; zz[30] = 0ull; zz[31] = 0ull;

    if (t < NSEQ) { i1s[t] = g_is1[t]; m1s[t] = g_m1[t]; }
    if (t < 64) { ssum[t] = 0.f; ssq[t] = 0.f; }
    __syncthreads();

    {
        const float* cgb = corr + (size_t)b * NSEQ * NSEQ;
        for (int idx = lt; idx < NSEQ*32; idx += 64) {
            int n = idx >> 5, m = idx & 31;
            float v = (m < NSEQ) ? cgb[n*NSEQ + m] * i1s[m] : 0.f;
            cs[(lb*NSEQ + n)*32 + m] = make_float2(v, v);
        }
    }
    __syncthreads();

    if (lt < NSEQ) {
        float q = 0.f;
        #pragma unroll
        for (int m = 0; m < NSEQ; m++) q = fmaf(cs[(lb*NSEQ + lt)*32 + m].x, m1s[m], q);
        qs[lb*32 + lt] = q;
    }
    __syncthreads();

    float2 S2 = *(const float2*)(g_S + 2*lt);
    float2 bg2 = *(const float2*)(bg + 2*lt);
    float agv = ag[0];
    float* zg = g_z + (size_t)b * NSEQ * DD + 2*lt;
    int lane = t & 31;

    #pragma unroll 1
    for (int n = 0; n < NSEQ; n++) {
        const ulonglong2* cr = (const ulonglong2*)&cs[(lb*NSEQ + n)*32];
        unsigned long long acc = 0ull;
        #pragma unroll
        for (int ch = 0; ch < 16; ch++) {
            ulonglong2 cc = cr[ch];
            FMA2(acc, zz[2*ch],   cc.x);
            FMA2(acc, zz[2*ch+1], cc.y);
        }
        float u0, u1; UNPK(u0, u1, acc);
        float qn = qs[lb*32 + n];
        u0 = u0 - S2.x*qn + bg2.x;
        u1 = u1 - S2.y*qn + bg2.y;
        u0 = (u0 >= 0.f) ? u0 : agv*u0;
        u1 = (u1 >= 0.f) ? u1 : agv*u1;
        *(float2*)(zg + n*DD) = make_float2(u0, u1);
        float su = u0 + u1;
        float s2v = u0*u0 + u1*u1;
        #pragma unroll
        for (int o = 16; o > 0; o >>= 1) {
            su  += __shfl_down_sync(0xffffffffu, su,  o);
            s2v += __shfl_down_sync(0xffffffffu, s2v, o);
        }
        if (lane == 0) {
            atomicAdd(&ssum[lb*32 + n], su);
            atomicAdd(&ssq[lb*32 + n], s2v);
        }
    }
    __syncthreads();
    if (t < 2*NSEQ) {
        int lb2 = t / NSEQ, n = t - lb2*NSEQ;
        atomicAdd(&g_s2[n], ssum[lb2*32 + n]);
        atomicAdd(&g_q2[n], ssq[lb2*32 + n]);
    }
}

// ---------------- k_fin2: BN2 finalize + combined head vector v ----------------
__global__ void k_fin2(const float* __restrict__ cent, const float* __restrict__ hw) {
    __shared__ float nrm[4];
    int t = threadIdx.x;
    if (t < NSEQ) {
        float cnt = (float)BB * (float)DD;
        float m = g_s2[t] / cnt;
        float v = g_q2[t] / cnt - m*m;
        g_bn2m[t] = m; g_bn2i[t] = rsqrtf(v + EPS_BN);
    }
    if (t >= 32 && t < 36) {
        int h = t - 32; float s = 0.f;
        for (int d = 0; d < DD; d++) { float c = cent[h*DD + d]; s = fmaf(c, c, s); }
        nrm[h] = sqrtf(s) + 1e-8f;
    }
    __syncthreads();
    float v = 0.f;
    #pragma unroll
    for (int h = 0; h < 4; h++) v += hw[h] * cent[h*DD + t] / nrm[h];
    g_v[t] = v;
}

// ---------------- k_pool: BN2 apply + cosine-sim softmax pooling ----------------
__global__ __launch_bounds__(128)
void k_pool()
{
    __shared__ float xb[NSEQ*DD];
    __shared__ float vS[DD], m2[NSEQ], i2[NSEQ], aggS[32], CS[32];
    int t = threadIdx.x, b = blockIdx.x;
    if (t < NSEQ) { m2[t] = g_bn2m[t]; i2[t] = g_bn2i[t]; }
    vS[t] = g_v[t];
    __syncthreads();
    const float* ug = g_z + (size_t)b * NSEQ * DD;
    #pragma unroll 1
    for (int n = 0; n < NSEQ; n++) xb[n*DD + t] = (ug[n*DD + t] - m2[n]) * i2[n];
    __syncthreads();
    int w = t >> 5, l = t & 31;
    for (int n = w; n < NSEQ; n += 4) {
        float s2 = 0.f, sa = 0.f;
        #pragma unroll
        for (int dd = 0; dd < 4; dd++) {
            float x = xb[n*DD + l + dd*32];
            s2 = fmaf(x, x, s2);
            sa = fmaf(vS[l + dd*32], x, sa);
        }
        #pragma unroll
        for (int o = 16; o > 0; o >>= 1) {
            s2 += __shfl_down_sync(0xffffffffu, s2, o);
            sa += __shfl_down_sync(0xffffffffu, sa, o);
        }
        if (l == 0) aggS[n] = sa / (sqrtf(s2) + 1e-8f);
    }
    __syncthreads();
    if (w == 0) {
        float a = (l < NSEQ) ? aggS[l] : -1e30f;
        float mx = a;
        #pragma unroll
        for (int o = 16; o > 0; o >>= 1) mx = fmaxf(mx, __shfl_xor_sync(0xffffffffu, mx, o));
        float e = (l < NSEQ) ? expf(a - mx) : 0.f;
        float s = e;
        #pragma unroll
        for (int o = 16; o > 0; o >>= 1) s += __shfl_xor_sync(0xffffffffu, s, o);
        if (l < NSEQ) CS[l] = e / s;
    }
    __syncthreads();
    float p = 0.f;
    #pragma unroll 1
    for (int n = 0; n < NSEQ; n++) p = fmaf(CS[n], xb[n*DD + t], p);
    g_pool[(size_t)b*DD + t] = p;
}

// ---------------- k_projp: p = pooled @ Wp + bp; BN3 stats ----------------
__global__ __launch_bounds__(256)
void k_projp(const float* __restrict__ Wp, const float* __restrict__ bp)
{
    __shared__ float xs[64*DD];
    __shared__ float ss[DD], sq[DD];
    int t = threadIdx.x;
    size_t row0 = (size_t)blockIdx.x * 64;
    for (int i = t; i < 64*DD; i += 256) xs[i] = g_pool[row0*DD + i];
    if (t < DD) { ss[t] = 0.f; sq[t] = 0.f; }
    __syncthreads();
    int tc = t & 31, tr = t >> 5;
    float acc[8][4];
    #pragma unroll
    for (int i = 0; i < 8; i++)
        #pragma unroll
        for (int j = 0; j < 4; j++) acc[i][j] = 0.f;
    for (int k = 0; k < DD; k++) {
        float4 bv = *(const float4*)(Wp + k*DD + tc*4);
        #pragma unroll
        for (int i = 0; i < 8; i++) {
            float a = xs[(tr*8 + i)*DD + k];
            acc[i][0] = fmaf(a, bv.x, acc[i][0]);
            acc[i][1] = fmaf(a, bv.y, acc[i][1]);
            acc[i][2] = fmaf(a, bv.z, acc[i][2]);
            acc[i][3] = fmaf(a, bv.w, acc[i][3]);
        }
    }
    float4 bpv = *(const float4*)(bp + tc*4);
    float csum[4] = {0,0,0,0}, cq[4] = {0,0,0,0};
    #pragma unroll
    for (int i = 0; i < 8; i++) {
        float o0 = acc[i][0] + bpv.x, o1 = acc[i][1] + bpv.y;
        float o2 = acc[i][2] + bpv.z, o3 = acc[i][3] + bpv.w;
        *(float4*)(g_p + (row0 + tr*8 + i)*DD + tc*4) = make_float4(o0, o1, o2, o3);
        csum[0]+=o0; csum[1]+=o1; csum[2]+=o2; csum[3]+=o3;
        cq[0]=fmaf(o0,o0,cq[0]); cq[1]=fmaf(o1,o1,cq[1]); cq[2]=fmaf(o2,o2,cq[2]); cq[3]=fmaf(o3,o3,cq[3]);
    }
    #pragma unroll
    for (int j = 0; j < 4; j++) { atomicAdd(&ss[tc*4+j], csum[j]); atomicAdd(&sq[tc*4+j], cq[j]); }
    __syncthreads();
    if (t < DD) { atomicAdd(&g_s3[t], ss[t]); atomicAdd(&g_q3[t], sq[t]); }
}

__global__ void k_fin3() {
    int t = threadIdx.x;
    if (t < DD) {
        float m = g_s3[t] / (float)BB;
        float v = g_q3[t] / (float)BB - m*m;
        g_bn3m[t] = m; g_bn3i[t] = rsqrtf(v + EPS_BN);
    }
}

// ---------------- k_mlp ----------------
__global__ __launch_bounds__(128)
void k_mlp(const float* __restrict__ Wm1, const float* __restrict__ bm1,
           const float* __restrict__ am, const float* __restrict__ Wm2,
           const float* __restrict__ bm2, float* __restrict__ out)
{
    __shared__ float xbn[16*DD];
    __shared__ float sg[16*DD];
    int t = threadIdx.x;
    size_t row0 = (size_t)blockIdx.x * 16;
    for (int i = t; i < 16*DD; i += 128) {
        int k = i & 127;
        xbn[i] = (g_p[row0*DD + i] - g_bn3m[k]) * g_bn3i[k];
    }
    __syncthreads();
    float amv = am[0], w2 = Wm2[t], b1v = bm1[t];
    float acc[16];
    #pragma unroll
    for (int r = 0; r < 16; r++) acc[r] = b1v;
    #pragma unroll 4
    for (int k = 0; k < DD; k++) {
        float wv = Wm1[k*DD + t];
        #pragma unroll
        for (int r = 0; r < 16; r++) acc[r] = fmaf(xbn[r*DD + k], wv, acc[r]);
    }
    #pragma unroll
    for (int r = 0; r < 16; r++) {
        float h = acc[r];
        h = (h >= 0.f) ? h : amv*h;
        sg[r*DD + t] = h * w2;
    }
    __syncthreads();
    int w = t >> 5, l = t & 31;
    float b2 = bm2[0];
    #pragma unroll
    for (int rr = 0; rr < 4; rr++) {
        int r = w*4 + rr;
        float s = sg[r*DD + l] + sg[r*DD + l + 32] + sg[r*DD + l + 64] + sg[r*DD + l + 96];
        #pragma unroll
        for (int o = 16; o > 0; o >>= 1) s += __shfl_down_sync(0xffffffffu, s, o);
        if (l == 0) out[row0 + r] = 1.f / (1.f + expf(-(s + b2)));
    }
}

// ---------------- launch ----------------
extern "C" void kernel_launch(void* const* d_in, const int* in_sizes, int n_in,
                              void* d_out, int out_size) {
    const float* X    = (const float*)d_in[0];
    const float* corr = (const float*)d_in[1];
    const float* w1   = (const float*)d_in[2];
    const float* b1   = (const float*)d_in[3];
    const float* w2   = (const float*)d_in[4];
    const float* b2   = (const float*)d_in[5];
    const float* w3   = (const float*)d_in[6];
    const float* b3   = (const float*)d_in[7];
    const float* ac   = (const float*)d_in[8];
    const float* Wg   = (const float*)d_in[9];
    const float* bg   = (const float*)d_in[10];
    const float* ag   = (const float*)d_in[11];
    const float* cent = (const float*)d_in[12];
    const float* hw   = (const float*)d_in[13];
    const float* Wp   = (const float*)d_in[14];
    const float* bp   = (const float*)d_in[15];
    const float* Wm1  = (const float*)d_in[16];
    const float* bm1  = (const float*)d_in[17];
    const float* am   = (const float*)d_in[18];
    const float* Wm2  = (const float*)d_in[19];
    const float* bm2  = (const float*)d_in[20];
    float* out = (float*)d_out;

    cudaFuncSetAttribute(k_gemm, cudaFuncAttributeMaxDynamicSharedMemorySize, GEMM_SMEM);

    k_reset<<<1, 128>>>();
    k_prep<<<(DD*KPAD + 255)/256, 256>>>(Wg);
    k_gemm<<<NROWS/64, 256, GEMM_SMEM>>>(X, w1, b1, w2, b2, w3, b3, ac);
    k_fin1<<<1, 256>>>(Wg);
    k_mix<<<BB/2, 128>>>(corr, bg, ag);
    k_fin2<<<1, 128>>>(cent, hw);
    k_pool<<<BB, 128>>>();
    k_projp<<<BB/64, 256>>>(Wp, bp);
    k_fin3<<<1, 128>>>();
    k_mlp<<<BB/16, 128>>>(Wm1, bm1, am, Wm2, bm2, out);
}